// round 14
// baseline (speedup 1.0000x reference)
#include <cuda_runtime.h>
#include <cstdint>

// Problem constants
#define B_  4
#define T_  4096
#define W_  1024
#define H_  8

// Fused tiling: block = (chunk of 64 timesteps) x (1 head = 128 ch x 2 gates)
#define CL  64
#define NCH (T_/CL)        // 64 chunks
#define XS2 136            // x_s row stride (floats): paired layout, conflict-free
#define AXS 130            // anx row stride (float2)
#define SS  16             // sub-chunk length
#define NS  (CL/SS)        // 4 sub-chunks

typedef unsigned long long ull;

// Device scratch (no allocations allowed)
__device__ float4 g_wp4[(size_t)H_*16*4*128];     // packed tf32 weight quads, 1 MB
__device__ ull    g_loc[(size_t)B_*H_*NCH*128];   // per-chunk local (P,L)
__device__ ull    g_inc[(size_t)B_*H_*NCH*128];   // per-chunk inclusive (1, h_incl)

// ---------------- helpers ----------------
__device__ __forceinline__ uint32_t f2tf32(float f) {
    uint32_t r; asm("cvt.rna.tf32.f32 %0, %1;" : "=r"(r) : "f"(f)); return r;
}
__device__ __forceinline__ void mma_tf32(float4 &d, const uint32_t a[4],
                                         uint32_t b0, uint32_t b1) {
    asm("mma.sync.aligned.m16n8k8.row.col.f32.tf32.tf32.f32 "
        "{%0,%1,%2,%3}, {%4,%5,%6,%7}, {%8,%9}, {%0,%1,%2,%3};"
        : "+f"(d.x), "+f"(d.y), "+f"(d.z), "+f"(d.w)
        : "r"(a[0]), "r"(a[1]), "r"(a[2]), "r"(a[3]), "r"(b0), "r"(b1));
}
__device__ __forceinline__ float fast_tanh(float x) {
    float r; asm("tanh.approx.f32 %0, %1;" : "=f"(r) : "f"(x)); return r;
}
__device__ __forceinline__ float fast_sigmoid(float x) {
    return fmaf(fast_tanh(0.5f * x), 0.5f, 0.5f);
}
__device__ __forceinline__ float fast_sqrt(float x) {
    float r; asm("sqrt.approx.f32 %0, %1;" : "=f"(r) : "f"(x)); return r;
}
__device__ __forceinline__ ull pack_f2(float a, float b) {
    ull r;
    asm("mov.b64 %0, {%1, %2};" : "=l"(r) : "r"(__float_as_uint(a)), "r"(__float_as_uint(b)));
    return r;
}
__device__ __forceinline__ float lo_f(ull v) { return __uint_as_float((unsigned)(v & 0xffffffffull)); }
__device__ __forceinline__ float hi_f(ull v) { return __uint_as_float((unsigned)(v >> 32)); }

// ---------------- K0: pack weight quads (tf32) + init sentinels ----------------
// g_wp4[(((h*16+ks)*4+lc))*128 + m], m = qn*32 + p*8 + lr packs n-frags 2p,2p+1:
//   (w[k0+lc][na], w[k0+lc+4][na], w[k0+lc][nb], w[k0+lc+4][nb]),
//   na = qn*64 + 16p + lr, nb = na + 8, k0 = ks*8, n = 2*ch + gate.
__global__ __launch_bounds__(256)
void prep_kernel(const float* __restrict__ w_in, const float* __restrict__ w_a)
{
    const int gid = blockIdx.x * 256 + threadIdx.x;    // grid 128 -> 32768 threads
    #pragma unroll
    for (int e = 0; e < 2; ++e) {
        int idx = e * 32768 + gid;                     // < 65536
        int m  = idx & 127;
        int lc = (idx >> 7) & 3;
        int ks = (idx >> 9) & 15;
        int h  = idx >> 13;
        int qn = m >> 5, p = (m >> 3) & 3, lr = m & 7;
        int k0 = ks * 8 + lc;
        float4 o;
        #pragma unroll
        for (int half = 0; half < 2; ++half) {
            int n  = qn*64 + 16*p + lr + half*8;
            int ch = n >> 1;
            const float* src = (n & 1) ? w_a : w_in;
            float v0 = src[h*16384 + k0*128 + ch];
            float v1 = src[h*16384 + (k0 + 4)*128 + ch];
            if (half == 0) { o.x = __uint_as_float(f2tf32(v0)); o.y = __uint_as_float(f2tf32(v1)); }
            else           { o.z = __uint_as_float(f2tf32(v0)); o.w = __uint_as_float(f2tf32(v1)); }
        }
        g_wp4[idx] = o;
    }
    const ull sent = pack_f2(-1.0f, 0.0f);
    #pragma unroll
    for (int e = 0; e < 8; ++e) {
        int idx = e * 32768 + gid;                     // 262144 slots each
        g_loc[idx] = sent;
        g_inc[idx] = sent;
    }
}

// ---------------- K1: fused gates GEMM + scan ----------------
// Grid (NCH, H, B), chunk fastest -> lookback predecessors have lower bid.
__global__ __launch_bounds__(256, 2)
void fused_kernel(const float* __restrict__ x, const int* __restrict__ segp,
                  const float* __restrict__ a_param,
                  const float* __restrict__ b_in, const float* __restrict__ b_a,
                  float* __restrict__ out)
{
    extern __shared__ float smem[];
    float*  x_s    = smem;                        // [64][XS2] tf32, paired  34816 B
    float2* anx    = (float2*)(smem + 64*XS2);    // [64][AXS] -> (P,L)     66560 B
    float*  bias_s = (float*)(anx + 64*AXS);      // [256]
    float*  c_s    = bias_s + 256;                // [128]
    float*  sq_s   = c_s + 128;                   // [NS][128] sub-chunk entry states
    int*    seg_s  = (int*)(sq_s + NS*128);       // [64]

    const int tid = threadIdx.x;
    const int c = blockIdx.x, h = blockIdx.y, b = blockIdx.z;
    const int t0 = c * CL;
    const int bh = b * H_ + h;

    // ---- stage: x chunk (tf32, paired (k,k+4) layout), seg, bias, decay consts ----
    {
        const float* xg = x + ((size_t)(b*T_ + t0)) * W_ + h * 128;
        #pragma unroll
        for (int i = tid; i < 64*16; i += 256) {       // 1024 octet tasks
            int m = i >> 4, q = i & 15;                // k = 8q .. 8q+7
            const float* p0 = xg + (size_t)m * W_ + q*8;
            float4 lo = *(const float4*)(p0);
            float4 hi = *(const float4*)(p0 + 4);
            float* dst = x_s + m*XS2 + q*8;
            *(float2*)(dst + 0) = make_float2(__uint_as_float(f2tf32(lo.x)), __uint_as_float(f2tf32(hi.x)));
            *(float2*)(dst + 2) = make_float2(__uint_as_float(f2tf32(lo.y)), __uint_as_float(f2tf32(hi.y)));
            *(float2*)(dst + 4) = make_float2(__uint_as_float(f2tf32(lo.z)), __uint_as_float(f2tf32(hi.z)));
            *(float2*)(dst + 6) = make_float2(__uint_as_float(f2tf32(lo.w)), __uint_as_float(f2tf32(hi.w)));
        }
        if (tid < 64)  seg_s[tid] = segp[b*T_ + t0 + tid];
        if (tid < 256) bias_s[tid] = (tid & 1) ? b_a[h*128 + (tid>>1)]
                                               : b_in[h*128 + (tid>>1)];
        if (tid < 128) c_s[tid] = -8.0f * log1pf(__expf(a_param[h*128 + tid]));
    }
    __syncthreads();

    // ---- MMA: z[64 t][256 n] = x[64][128] * w[128][256] ----
    const int warp = tid >> 5, lane = tid & 31;
    const int wm = (warp >> 2) * 32;
    const int wq = warp & 3;                   // n quadrant
    const int lr = lane >> 2, lcq = lane & 3;

    float4 acc[2][8];
    #pragma unroll
    for (int mf = 0; mf < 2; ++mf)
        #pragma unroll
        for (int nf = 0; nf < 8; ++nf)
            acc[mf][nf] = make_float4(0.f, 0.f, 0.f, 0.f);

    #pragma unroll
    for (int ks = 0; ks < 16; ++ks) {
        uint32_t a[2][4];
        #pragma unroll
        for (int mf = 0; mf < 2; ++mf) {
            const float* xr = x_s + (wm + mf*16 + lr)*XS2 + ks*8 + lcq*2;
            float2 a02 = *(const float2*)(xr);            // (k, k+4) row r
            float2 a13 = *(const float2*)(xr + 8*XS2);    // (k, k+4) row r+8
            a[mf][0] = __float_as_uint(a02.x);
            a[mf][1] = __float_as_uint(a13.x);
            a[mf][2] = __float_as_uint(a02.y);
            a[mf][3] = __float_as_uint(a13.y);
        }
        const float4* wk = g_wp4 + (((size_t)h*16 + ks)*4 + lcq)*128 + wq*32 + lr;
        #pragma unroll
        for (int p = 0; p < 4; ++p) {
            float4 bv = __ldg(wk + p*8);
            uint32_t b0 = __float_as_uint(bv.x), b1 = __float_as_uint(bv.y);
            uint32_t b2 = __float_as_uint(bv.z), b3 = __float_as_uint(bv.w);
            mma_tf32(acc[0][2*p],   a[0], b0, b1);
            mma_tf32(acc[1][2*p],   a[1], b0, b1);
            mma_tf32(acc[0][2*p+1], a[0], b2, b3);
            mma_tf32(acc[1][2*p+1], a[1], b2, b3);
        }
    }

    // ---- epilogue: gates -> (a, normed_x) into smem ----
    #pragma unroll
    for (int mf = 0; mf < 2; ++mf) {
        #pragma unroll
        for (int nf = 0; nf < 8; ++nf) {
            const int ch = wq*32 + nf*4 + lcq;
            const int chpos = (ch >> 3)*8 + (ch & 3)*2 + ((ch >> 2) & 1);  // paired x_s pos
            const float bx = bias_s[2*ch];
            const float ba = bias_s[2*ch + 1];
            const float cc = c_s[ch];
            #pragma unroll
            for (int half = 0; half < 2; ++half) {
                const int r = wm + mf*16 + lr + half*8;
                const float zx = (half ? acc[mf][nf].z : acc[mf][nf].x) + bx;
                const float za = (half ? acc[mf][nf].w : acc[mf][nf].y) + ba;
                const float gx = fast_sigmoid(zx);
                const float ga = fast_sigmoid(za);
                const float la = cc * ga;
                const float av = __expf(la);
                const float mult = fast_sqrt(fmaxf(1.0f - av*av, 0.0f));
                const float xv = x_s[r*XS2 + chpos];
                const float nx = xv * gx * mult;
                const float ao = (seg_s[r] == 0) ? 0.0f : av;
                anx[r*AXS + ch] = make_float2(ao, nx);
            }
        }
    }
    __syncthreads();

    // ---- sub-chunk scans: 512 (ch,q) tasks over 256 threads, 16 serial steps ----
    {
        const int ch = tid & 127;
        const int q0 = (tid >> 7) * 2;
        #pragma unroll
        for (int e = 0; e < 2; ++e) {
            const int qq = q0 + e;
            float P = 1.0f, L = 0.0f;
            #pragma unroll
            for (int t = 0; t < SS; ++t) {
                float2* p = &anx[(qq*SS + t)*AXS + ch];
                float2 v = *p;
                L = fmaf(v.x, L, v.y);
                P *= v.x;
                *p = make_float2(P, L);
            }
        }
    }
    __syncthreads();

    // ---- combine sub-chunks, publish, lookback, sub-chunk entry states ----
    if (tid < 128) {
        const int ch = tid;
        float2 E[NS];
        #pragma unroll
        for (int q = 0; q < NS; ++q)
            E[q] = anx[(q*SS + SS-1)*AXS + ch];
        float P = E[0].x, L = E[0].y;
        #pragma unroll
        for (int q = 1; q < NS; ++q) { L = fmaf(E[q].x, L, E[q].y); P *= E[q].x; }

        const size_t slot = ((size_t)bh * NCH + c) * 128 + ch;
        *(volatile ull*)&g_loc[slot] = pack_f2(P, L);

        float carry = 0.0f;
        if (c > 0) {
            float Aacc = 1.0f, Hacc = 0.0f;
            int k = c - 1;
            const ull* incp = g_inc + (size_t)bh * NCH * 128 + ch;
            const ull* locp = g_loc + (size_t)bh * NCH * 128 + ch;
            while (true) {
                ull v = *(volatile const ull*)(incp + (size_t)k * 128);
                if (lo_f(v) >= 0.0f) { carry = fmaf(Aacc, hi_f(v), Hacc); break; }
                ull w = *(volatile const ull*)(locp + (size_t)k * 128);
                float Pk = lo_f(w);
                if (Pk >= 0.0f) {
                    Hacc = fmaf(Aacc, hi_f(w), Hacc);
                    Aacc *= Pk;
                    if (--k < 0) { carry = Hacc; break; }
                }
            }
        }
        *(volatile ull*)&g_inc[slot] = pack_f2(1.0f, fmaf(P, carry, L));

        float s = carry;
        #pragma unroll
        for (int q = 0; q < NS; ++q) {
            sq_s[q*128 + ch] = s;
            s = fmaf(E[q].x, s, E[q].y);
        }
    }
    __syncthreads();

    // ---- parallel output: out(t,ch) = P_q(t)*s_q(ch) + L_q(t), all 256 threads ----
    {
        float* og = out + ((size_t)(b*T_ + t0)) * W_ + h * 128;
        #pragma unroll
        for (int j = 0; j < 8; ++j) {
            int i  = tid + j * 256;
            int t  = i >> 5;
            int c4 = (i & 31) * 4;
            float4 pl01 = *(const float4*)(&anx[t*AXS + c4]);
            float4 pl23 = *(const float4*)(&anx[t*AXS + c4 + 2]);
            float4 sv   = *(const float4*)(sq_s + (t >> 4)*128 + c4);
            float4 o;
            o.x = fmaf(pl01.x, sv.x, pl01.y);
            o.y = fmaf(pl01.z, sv.y, pl01.w);
            o.z = fmaf(pl23.x, sv.z, pl23.y);
            o.w = fmaf(pl23.z, sv.w, pl23.w);
            *(float4*)(og + (size_t)t * W_ + c4) = o;
        }
    }
}

// ---------------- launch ----------------
extern "C" void kernel_launch(void* const* d_in, const int* in_sizes, int n_in,
                              void* d_out, int out_size)
{
    const float* x       = (const float*)d_in[0];
    const int*   segp    = (const int*)  d_in[1];
    const float* a_param = (const float*)d_in[2];
    const float* w_in    = (const float*)d_in[3];
    const float* b_in    = (const float*)d_in[4];
    const float* w_a     = (const float*)d_in[5];
    const float* b_a     = (const float*)d_in[6];
    float* out = (float*)d_out;

    const int smem_bytes = 64*XS2*4 + 64*AXS*8 + 256*4 + 128*4 + NS*128*4 + 64*4; // 105472
    cudaFuncSetAttribute(fused_kernel,
                         cudaFuncAttributeMaxDynamicSharedMemorySize, smem_bytes);

    prep_kernel<<<128, 256>>>(w_in, w_a);
    fused_kernel<<<dim3(NCH, H_, B_), 256, smem_bytes>>>(x, segp, a_param,
                                                         b_in, b_a, out);
}

// round 15
// speedup vs baseline: 1.0567x; 1.0567x over previous
#include <cuda_runtime.h>
#include <cstdint>

// Problem constants
#define B_  4
#define T_  4096
#define W_  1024
#define H_  8

// Fused tiling: block = (chunk of 64 timesteps) x (1 head = 128 ch x 2 gates)
#define CL  64
#define NCH (T_/CL)        // 64 chunks
#define XS  132            // x_s row stride (floats): A-frag bank 4*lr+lc, conflict-free
#define AXS 130            // anx row stride (float2)
#define SS  16             // sub-chunk length
#define NS  (CL/SS)        // 4 sub-chunks

typedef unsigned long long ull;

// Device scratch (no allocations allowed)
__device__ float2 g_wp2[(size_t)H_*16*4*256];     // packed tf32 weight pairs, 1 MB
__device__ ull    g_loc[(size_t)B_*H_*NCH*128];   // per-chunk local (P,L)
__device__ ull    g_inc[(size_t)B_*H_*NCH*128];   // per-chunk inclusive (1, h_incl)

// ---------------- helpers ----------------
__device__ __forceinline__ uint32_t f2tf32(float f) {
    uint32_t r; asm("cvt.rna.tf32.f32 %0, %1;" : "=r"(r) : "f"(f)); return r;
}
__device__ __forceinline__ void mma_tf32(float4 &d, const uint32_t a[4],
                                         uint32_t b0, uint32_t b1) {
    asm("mma.sync.aligned.m16n8k8.row.col.f32.tf32.tf32.f32 "
        "{%0,%1,%2,%3}, {%4,%5,%6,%7}, {%8,%9}, {%0,%1,%2,%3};"
        : "+f"(d.x), "+f"(d.y), "+f"(d.z), "+f"(d.w)
        : "r"(a[0]), "r"(a[1]), "r"(a[2]), "r"(a[3]), "r"(b0), "r"(b1));
}
__device__ __forceinline__ float fast_tanh(float x) {
    float r; asm("tanh.approx.f32 %0, %1;" : "=f"(r) : "f"(x)); return r;
}
__device__ __forceinline__ float fast_sigmoid(float x) {
    return fmaf(fast_tanh(0.5f * x), 0.5f, 0.5f);
}
__device__ __forceinline__ float fast_sqrt(float x) {
    float r; asm("sqrt.approx.f32 %0, %1;" : "=f"(r) : "f"(x)); return r;
}
__device__ __forceinline__ ull pack_f2(float a, float b) {
    ull r;
    asm("mov.b64 %0, {%1, %2};" : "=l"(r) : "r"(__float_as_uint(a)), "r"(__float_as_uint(b)));
    return r;
}
__device__ __forceinline__ float lo_f(ull v) { return __uint_as_float((unsigned)(v & 0xffffffffull)); }
__device__ __forceinline__ float hi_f(ull v) { return __uint_as_float((unsigned)(v >> 32)); }

// ---------------- K0: pack weights (tf32 pairs) + init sentinels ----------------
// g_wp2[((h*16+ks)*4+lc)*256 + n] = (w[k0+lc][n], w[k0+lc+4][n]), n = 2*ch+gate
__global__ __launch_bounds__(256)
void prep_kernel(const float* __restrict__ w_in, const float* __restrict__ w_a)
{
    const int gid = blockIdx.x * 256 + threadIdx.x;    // grid 128 -> 32768 threads
    #pragma unroll
    for (int e = 0; e < 4; ++e) {
        int idx = e * 32768 + gid;                     // < 131072
        int n   = idx & 255;
        int lc  = (idx >> 8) & 3;
        int ks  = (idx >> 10) & 15;
        int h   = idx >> 14;
        int ch  = n >> 1;
        const float* src = (n & 1) ? w_a : w_in;
        int k0 = ks * 8 + lc;
        float v0 = src[h*16384 + k0*128 + ch];
        float v1 = src[h*16384 + (k0 + 4)*128 + ch];
        float2 o;
        o.x = __uint_as_float(f2tf32(v0));
        o.y = __uint_as_float(f2tf32(v1));
        g_wp2[idx] = o;
    }
    const ull sent = pack_f2(-1.0f, 0.0f);
    #pragma unroll
    for (int e = 0; e < 8; ++e) {
        int idx = e * 32768 + gid;                     // 262144 slots each
        g_loc[idx] = sent;
        g_inc[idx] = sent;
    }
}

// ---------------- K1: fused gates GEMM + scan (two-flag decoupled lookback) ----------------
// Grid (NCH, H, B), chunk index fastest -> lookback predecessors have lower bid.
__global__ __launch_bounds__(256, 2)
void fused_kernel(const float* __restrict__ x, const int* __restrict__ segp,
                  const float* __restrict__ a_param,
                  const float* __restrict__ b_in, const float* __restrict__ b_a,
                  float* __restrict__ out)
{
    extern __shared__ float smem[];
    float*  x_s    = smem;                        // [64][XS] tf32 bits   33792 B
    float2* anx    = (float2*)(smem + 64*XS);     // [64][AXS] (a,nx)     66560 B
    float*  bias_s = (float*)(anx + 64*AXS);      // [256]
    float*  c_s    = bias_s + 256;                // [128]
    float2* Eq_s   = (float2*)(c_s + 128);        // [NS][128] sub-chunk summaries 4096 B
    float*  sq_s   = (float*)(Eq_s + NS*128);     // [NS][128] sub-chunk entry states
    int*    seg_s  = (int*)(sq_s + NS*128);       // [64]

    const int tid = threadIdx.x;
    const int c = blockIdx.x, h = blockIdx.y, b = blockIdx.z;
    const int t0 = c * CL;
    const int bh = b * H_ + h;

    // ---- stage: x chunk (tf32), seg, bias, decay consts ----
    {
        const float* xg = x + ((size_t)(b*T_ + t0)) * W_ + h * 128;
        #pragma unroll
        for (int i = tid; i < 64*32; i += 256) {
            int m = i >> 5, q = i & 31;
            float4 v = *(const float4*)(xg + (size_t)m * W_ + q*4);
            float4 o;
            o.x = __uint_as_float(f2tf32(v.x));
            o.y = __uint_as_float(f2tf32(v.y));
            o.z = __uint_as_float(f2tf32(v.z));
            o.w = __uint_as_float(f2tf32(v.w));
            *(float4*)(x_s + m*XS + q*4) = o;
        }
        if (tid < 64)  seg_s[tid] = segp[b*T_ + t0 + tid];
        if (tid < 256) bias_s[tid] = (tid & 1) ? b_a[h*128 + (tid>>1)]
                                               : b_in[h*128 + (tid>>1)];
        if (tid < 128) c_s[tid] = -8.0f * log1pf(__expf(a_param[h*128 + tid]));
    }
    __syncthreads();

    // ---- MMA: z[64 t][256 n] = x[64][128] * w[128][256] ----
    const int warp = tid >> 5, lane = tid & 31;
    const int wm = (warp >> 2) * 32;
    const int wn = (warp & 3) * 64;
    const int lr = lane >> 2, lcq = lane & 3;

    float4 acc[2][8];
    #pragma unroll
    for (int mf = 0; mf < 2; ++mf)
        #pragma unroll
        for (int nf = 0; nf < 8; ++nf)
            acc[mf][nf] = make_float4(0.f, 0.f, 0.f, 0.f);

    const float2* wp = g_wp2 + (size_t)h * 16 * 4 * 256;
    #pragma unroll
    for (int ks = 0; ks < 16; ++ks) {
        const int k0 = ks * 8;
        uint32_t a[2][4];
        #pragma unroll
        for (int mf = 0; mf < 2; ++mf) {
            const float* xr = x_s + (wm + mf*16 + lr)*XS + k0 + lcq;
            a[mf][0] = __float_as_uint(xr[0]);
            a[mf][1] = __float_as_uint(xr[8*XS]);
            a[mf][2] = __float_as_uint(xr[4]);
            a[mf][3] = __float_as_uint(xr[8*XS + 4]);
        }
        const float2* wk = wp + (ks*4 + lcq)*256;
        #pragma unroll
        for (int nf = 0; nf < 8; ++nf) {
            float2 bv = __ldg(wk + wn + nf*8 + lr);
            uint32_t b0 = __float_as_uint(bv.x);
            uint32_t b1 = __float_as_uint(bv.y);
            mma_tf32(acc[0][nf], a[0], b0, b1);
            mma_tf32(acc[1][nf], a[1], b0, b1);
        }
    }

    // ---- epilogue: gates -> (a, normed_x) into smem ----
    #pragma unroll
    for (int mf = 0; mf < 2; ++mf) {
        #pragma unroll
        for (int nf = 0; nf < 8; ++nf) {
            const int ch = (warp & 3)*32 + nf*4 + lcq;
            const float bx = bias_s[2*ch];
            const float ba = bias_s[2*ch + 1];
            const float cc = c_s[ch];
            #pragma unroll
            for (int half = 0; half < 2; ++half) {
                const int r = wm + mf*16 + lr + half*8;
                const float zx = (half ? acc[mf][nf].z : acc[mf][nf].x) + bx;
                const float za = (half ? acc[mf][nf].w : acc[mf][nf].y) + ba;
                const float gx = fast_sigmoid(zx);
                const float ga = fast_sigmoid(za);
                const float la = cc * ga;
                const float av = __expf(la);
                const float mult = fast_sqrt(fmaxf(1.0f - av*av, 0.0f));
                const float xv = x_s[r*XS + ch];
                const float nx = xv * gx * mult;
                const float ao = (seg_s[r] == 0) ? 0.0f : av;
                anx[r*AXS + ch] = make_float2(ao, nx);
            }
        }
    }
    __syncthreads();

    // ---- phase A: read-only sub-chunk summaries (512 tasks / 256 threads) ----
    {
        const int ch = tid & 127;
        const int qb = (tid >> 7) * 2;
        #pragma unroll
        for (int e = 0; e < 2; ++e) {
            const int q = qb + e;
            float P = 1.0f, L = 0.0f;
            #pragma unroll
            for (int t = 0; t < SS; ++t) {
                float2 v = anx[(q*SS + t)*AXS + ch];
                L = fmaf(v.x, L, v.y);
                P *= v.x;
            }
            Eq_s[q*128 + ch] = make_float2(P, L);
        }
    }
    __syncthreads();

    // ---- combine, publish, lookback, sub-chunk entry states (128 threads) ----
    if (tid < 128) {
        const int ch = tid;
        float2 E0 = Eq_s[0*128 + ch], E1 = Eq_s[1*128 + ch];
        float2 E2 = Eq_s[2*128 + ch], E3 = Eq_s[3*128 + ch];
        float P = E0.x, L = E0.y;
        L = fmaf(E1.x, L, E1.y); P *= E1.x;
        L = fmaf(E2.x, L, E2.y); P *= E2.x;
        L = fmaf(E3.x, L, E3.y); P *= E3.x;

        const size_t slot = ((size_t)bh * NCH + c) * 128 + ch;
        *(volatile ull*)&g_loc[slot] = pack_f2(P, L);   // publish local ASAP

        float carry = 0.0f;
        if (c > 0) {
            float Aacc = 1.0f, Hacc = 0.0f;
            int k = c - 1;
            const ull* incp = g_inc + (size_t)bh * NCH * 128 + ch;
            const ull* locp = g_loc + (size_t)bh * NCH * 128 + ch;
            while (true) {
                ull v = *(volatile const ull*)(incp + (size_t)k * 128);
                if (lo_f(v) >= 0.0f) { carry = fmaf(Aacc, hi_f(v), Hacc); break; }
                ull w = *(volatile const ull*)(locp + (size_t)k * 128);
                float Pk = lo_f(w);
                if (Pk >= 0.0f) {
                    Hacc = fmaf(Aacc, hi_f(w), Hacc);
                    Aacc *= Pk;
                    if (--k < 0) { carry = Hacc; break; }
                }
            }
        }
        *(volatile ull*)&g_inc[slot] = pack_f2(1.0f, fmaf(P, carry, L));

        float s = carry;
        sq_s[0*128 + ch] = s;  s = fmaf(E0.x, s, E0.y);
        sq_s[1*128 + ch] = s;  s = fmaf(E1.x, s, E1.y);
        sq_s[2*128 + ch] = s;  s = fmaf(E2.x, s, E2.y);
        sq_s[3*128 + ch] = s;
    }
    __syncthreads();

    // ---- phase B: replay sub-chunks with entry state, STG direct (512 tasks) ----
    {
        const int ch = tid & 127;
        const int qb = (tid >> 7) * 2;
        float* og = out + ((size_t)(b*T_ + t0)) * W_ + h * 128 + ch;
        #pragma unroll
        for (int e = 0; e < 2; ++e) {
            const int q = qb + e;
            float hh = sq_s[q*128 + ch];
            #pragma unroll
            for (int t = 0; t < SS; ++t) {
                float2 v = anx[(q*SS + t)*AXS + ch];
                hh = fmaf(v.x, hh, v.y);
                og[(size_t)(q*SS + t) * W_] = hh;
            }
        }
    }
}

// ---------------- launch ----------------
extern "C" void kernel_launch(void* const* d_in, const int* in_sizes, int n_in,
                              void* d_out, int out_size)
{
    const float* x       = (const float*)d_in[0];
    const int*   segp    = (const int*)  d_in[1];
    const float* a_param = (const float*)d_in[2];
    const float* w_in    = (const float*)d_in[3];
    const float* b_in    = (const float*)d_in[4];
    const float* w_a     = (const float*)d_in[5];
    const float* b_a     = (const float*)d_in[6];
    float* out = (float*)d_out;

    // 33792 + 66560 + 1024 + 512 + 4096 + 2048 + 256 = 108288
    const int smem_bytes = 64*XS*4 + 64*AXS*8 + 256*4 + 128*4 + NS*128*8 + NS*128*4 + 64*4;
    cudaFuncSetAttribute(fused_kernel,
                         cudaFuncAttributeMaxDynamicSharedMemorySize, smem_bytes);

    prep_kernel<<<128, 256>>>(w_in, w_a);
    fused_kernel<<<dim3(NCH, H_, B_), 256, smem_bytes>>>(x, segp, a_param,
                                                         b_in, b_a, out);
}

// round 16
// speedup vs baseline: 1.3941x; 1.3192x over previous
#include <cuda_runtime.h>
#include <cstdint>

// Problem constants
#define B_  4
#define T_  4096
#define W_  1024
#define H_  8

// Fused tiling: block = (chunk of 64 timesteps) x (1 head = 128 ch x 2 gates)
#define CL  64
#define NCH (T_/CL)        // 64 chunks
#define XS  132            // x_s row stride (floats): A-frag bank 4*lr+lc, conflict-free
#define AXS 130            // anx row stride (float2)
#define SS  16             // sub-chunk length
#define NS  (CL/SS)        // 4 sub-chunks

typedef unsigned long long ull;

// Device scratch (no allocations allowed)
// g_wp4[(((h*16+ks)*4+nq)*4+np)*32 + lane] =
//   (w[k0+lcq][na], w[k0+lcq+4][na], w[k0+lcq][nb], w[k0+lcq+4][nb])
//   lane = lr*4+lcq, na = nq*64+np*16+lr, nb = na+8, k0 = ks*8, n = 2*ch+gate.
// Per (ks,nq,np): one warp LDG.128 covers 512 contiguous bytes.
__device__ float4 g_wp4[(size_t)H_*16*4*4*32];    // 1 MB
__device__ ull    g_loc[(size_t)B_*H_*NCH*128];   // per-chunk local (P,L)
__device__ ull    g_inc[(size_t)B_*H_*NCH*128];   // per-chunk inclusive (1, h_incl)

// ---------------- helpers ----------------
__device__ __forceinline__ uint32_t f2tf32(float f) {
    uint32_t r; asm("cvt.rna.tf32.f32 %0, %1;" : "=r"(r) : "f"(f)); return r;
}
__device__ __forceinline__ void mma_tf32(float4 &d, const uint32_t a[4],
                                         uint32_t b0, uint32_t b1) {
    asm("mma.sync.aligned.m16n8k8.row.col.f32.tf32.tf32.f32 "
        "{%0,%1,%2,%3}, {%4,%5,%6,%7}, {%8,%9}, {%0,%1,%2,%3};"
        : "+f"(d.x), "+f"(d.y), "+f"(d.z), "+f"(d.w)
        : "r"(a[0]), "r"(a[1]), "r"(a[2]), "r"(a[3]), "r"(b0), "r"(b1));
}
__device__ __forceinline__ float fast_tanh(float x) {
    float r; asm("tanh.approx.f32 %0, %1;" : "=f"(r) : "f"(x)); return r;
}
__device__ __forceinline__ float fast_sigmoid(float x) {
    return fmaf(fast_tanh(0.5f * x), 0.5f, 0.5f);
}
__device__ __forceinline__ float fast_sqrt(float x) {
    float r; asm("sqrt.approx.f32 %0, %1;" : "=f"(r) : "f"(x)); return r;
}
__device__ __forceinline__ ull pack_f2(float a, float b) {
    ull r;
    asm("mov.b64 %0, {%1, %2};" : "=l"(r) : "r"(__float_as_uint(a)), "r"(__float_as_uint(b)));
    return r;
}
__device__ __forceinline__ float lo_f(ull v) { return __uint_as_float((unsigned)(v & 0xffffffffull)); }
__device__ __forceinline__ float hi_f(ull v) { return __uint_as_float((unsigned)(v >> 32)); }

// ---------------- K0: pack weight table (coalesced float4) + init sentinels ----------------
__global__ __launch_bounds__(256)
void prep_kernel(const float* __restrict__ w_in, const float* __restrict__ w_a)
{
    const int gid = blockIdx.x * 256 + threadIdx.x;    // grid 128 -> 32768 threads
    #pragma unroll
    for (int e = 0; e < 2; ++e) {
        int idx = e * 32768 + gid;                     // < 65536 float4 slots
        int lane = idx & 31;
        int np   = (idx >> 5) & 3;
        int nq   = (idx >> 7) & 3;
        int ks   = (idx >> 9) & 15;
        int h    = idx >> 13;
        int lr  = lane >> 2, lcq = lane & 3;
        int k0  = ks * 8;
        float4 o;
        #pragma unroll
        for (int half = 0; half < 2; ++half) {
            int n  = nq*64 + np*16 + lr + half*8;
            int ch = n >> 1;
            const float* src = (n & 1) ? w_a : w_in;
            float v0 = src[h*16384 + (k0 + lcq)*128 + ch];
            float v1 = src[h*16384 + (k0 + lcq + 4)*128 + ch];
            if (half == 0) { o.x = __uint_as_float(f2tf32(v0)); o.y = __uint_as_float(f2tf32(v1)); }
            else           { o.z = __uint_as_float(f2tf32(v0)); o.w = __uint_as_float(f2tf32(v1)); }
        }
        g_wp4[idx] = o;
    }
    const ull sent = pack_f2(-1.0f, 0.0f);
    #pragma unroll
    for (int e = 0; e < 8; ++e) {
        int idx = e * 32768 + gid;                     // 262144 slots each
        g_loc[idx] = sent;
        g_inc[idx] = sent;
    }
}

// ---------------- K1: fused gates GEMM + scan (two-flag decoupled lookback) ----------------
// Grid (NCH, H, B), chunk index fastest -> lookback predecessors have lower bid.
__global__ __launch_bounds__(256, 2)
void fused_kernel(const float* __restrict__ x, const int* __restrict__ segp,
                  const float* __restrict__ a_param,
                  const float* __restrict__ b_in, const float* __restrict__ b_a,
                  float* __restrict__ out)
{
    extern __shared__ float smem[];
    float*  x_s    = smem;                        // [64][XS] tf32 bits   33792 B
    float2* anx    = (float2*)(smem + 64*XS);     // [64][AXS] (a,nx)     66560 B
    float*  bias_s = (float*)(anx + 64*AXS);      // [256]
    float*  c_s    = bias_s + 256;                // [128]
    float2* Eq_s   = (float2*)(c_s + 128);        // [NS][128] sub-chunk summaries
    float*  sq_s   = (float*)(Eq_s + NS*128);     // [NS][128] sub-chunk entry states
    int*    seg_s  = (int*)(sq_s + NS*128);       // [64]

    const int tid = threadIdx.x;
    const int c = blockIdx.x, h = blockIdx.y, b = blockIdx.z;
    const int t0 = c * CL;
    const int bh = b * H_ + h;

    // ---- stage: x chunk (tf32), seg, bias, decay consts ----
    {
        const float* xg = x + ((size_t)(b*T_ + t0)) * W_ + h * 128;
        #pragma unroll
        for (int i = tid; i < 64*32; i += 256) {
            int m = i >> 5, q = i & 31;
            float4 v = *(const float4*)(xg + (size_t)m * W_ + q*4);
            float4 o;
            o.x = __uint_as_float(f2tf32(v.x));
            o.y = __uint_as_float(f2tf32(v.y));
            o.z = __uint_as_float(f2tf32(v.z));
            o.w = __uint_as_float(f2tf32(v.w));
            *(float4*)(x_s + m*XS + q*4) = o;
        }
        if (tid < 64)  seg_s[tid] = segp[b*T_ + t0 + tid];
        if (tid < 256) bias_s[tid] = (tid & 1) ? b_a[h*128 + (tid>>1)]
                                               : b_in[h*128 + (tid>>1)];
        if (tid < 128) c_s[tid] = -8.0f * log1pf(__expf(a_param[h*128 + tid]));
    }
    __syncthreads();

    // ---- MMA: z[64 t][256 n] = x[64][128] * w[128][256] ----
    const int warp = tid >> 5, lane = tid & 31;
    const int wm = (warp >> 2) * 32;
    const int nq = warp & 3;                   // n quadrant
    const int lr = lane >> 2, lcq = lane & 3;

    float4 acc[2][8];
    #pragma unroll
    for (int mf = 0; mf < 2; ++mf)
        #pragma unroll
        for (int nf = 0; nf < 8; ++nf)
            acc[mf][nf] = make_float4(0.f, 0.f, 0.f, 0.f);

    // coalesced weight pointer: + ks*512 + np*32 per step
    const float4* wbase = g_wp4 + ((size_t)h*256 + nq*4)*32 + lane;
    #pragma unroll
    for (int ks = 0; ks < 16; ++ks) {
        const int k0 = ks * 8;
        uint32_t a[2][4];
        #pragma unroll
        for (int mf = 0; mf < 2; ++mf) {
            const float* xr = x_s + (wm + mf*16 + lr)*XS + k0 + lcq;
            a[mf][0] = __float_as_uint(xr[0]);
            a[mf][1] = __float_as_uint(xr[8*XS]);
            a[mf][2] = __float_as_uint(xr[4]);
            a[mf][3] = __float_as_uint(xr[8*XS + 4]);
        }
        const float4* wk = wbase + ks*512;
        #pragma unroll
        for (int np = 0; np < 4; ++np) {
            float4 bv = __ldg(wk + np*32);
            uint32_t b0 = __float_as_uint(bv.x), b1 = __float_as_uint(bv.y);
            uint32_t b2 = __float_as_uint(bv.z), b3 = __float_as_uint(bv.w);
            mma_tf32(acc[0][2*np],   a[0], b0, b1);
            mma_tf32(acc[1][2*np],   a[1], b0, b1);
            mma_tf32(acc[0][2*np+1], a[0], b2, b3);
            mma_tf32(acc[1][2*np+1], a[1], b2, b3);
        }
    }

    // ---- epilogue: gates -> (a, normed_x) into smem ----
    #pragma unroll
    for (int mf = 0; mf < 2; ++mf) {
        #pragma unroll
        for (int nf = 0; nf < 8; ++nf) {
            const int ch = nq*32 + nf*4 + lcq;
            const float bx = bias_s[2*ch];
            const float ba = bias_s[2*ch + 1];
            const float cc = c_s[ch];
            #pragma unroll
            for (int half = 0; half < 2; ++half) {
                const int r = wm + mf*16 + lr + half*8;
                const float zx = (half ? acc[mf][nf].z : acc[mf][nf].x) + bx;
                const float za = (half ? acc[mf][nf].w : acc[mf][nf].y) + ba;
                const float gx = fast_sigmoid(zx);
                const float ga = fast_sigmoid(za);
                const float la = cc * ga;
                const float av = __expf(la);
                const float mult = fast_sqrt(fmaxf(1.0f - av*av, 0.0f));
                const float xv = x_s[r*XS + ch];
                const float nx = xv * gx * mult;
                const float ao = (seg_s[r] == 0) ? 0.0f : av;
                anx[r*AXS + ch] = make_float2(ao, nx);
            }
        }
    }
    __syncthreads();

    // ---- phase A: read-only sub-chunk summaries (512 tasks / 256 threads) ----
    {
        const int ch = tid & 127;
        const int qb = (tid >> 7) * 2;
        #pragma unroll
        for (int e = 0; e < 2; ++e) {
            const int q = qb + e;
            float P = 1.0f, L = 0.0f;
            #pragma unroll
            for (int t = 0; t < SS; ++t) {
                float2 v = anx[(q*SS + t)*AXS + ch];
                L = fmaf(v.x, L, v.y);
                P *= v.x;
            }
            Eq_s[q*128 + ch] = make_float2(P, L);
        }
    }
    __syncthreads();

    // ---- combine, publish, lookback, sub-chunk entry states (128 threads) ----
    if (tid < 128) {
        const int ch = tid;
        float2 E0 = Eq_s[0*128 + ch], E1 = Eq_s[1*128 + ch];
        float2 E2 = Eq_s[2*128 + ch], E3 = Eq_s[3*128 + ch];
        float P = E0.x, L = E0.y;
        L = fmaf(E1.x, L, E1.y); P *= E1.x;
        L = fmaf(E2.x, L, E2.y); P *= E2.x;
        L = fmaf(E3.x, L, E3.y); P *= E3.x;

        const size_t slot = ((size_t)bh * NCH + c) * 128 + ch;
        *(volatile ull*)&g_loc[slot] = pack_f2(P, L);   // publish local ASAP

        float carry = 0.0f;
        if (c > 0) {
            float Aacc = 1.0f, Hacc = 0.0f;
            int k = c - 1;
            const ull* incp = g_inc + (size_t)bh * NCH * 128 + ch;
            const ull* locp = g_loc + (size_t)bh * NCH * 128 + ch;
            while (true) {
                ull v = *(volatile const ull*)(incp + (size_t)k * 128);
                if (lo_f(v) >= 0.0f) { carry = fmaf(Aacc, hi_f(v), Hacc); break; }
                ull w = *(volatile const ull*)(locp + (size_t)k * 128);
                float Pk = lo_f(w);
                if (Pk >= 0.0f) {
                    Hacc = fmaf(Aacc, hi_f(w), Hacc);
                    Aacc *= Pk;
                    if (--k < 0) { carry = Hacc; break; }
                }
            }
        }
        *(volatile ull*)&g_inc[slot] = pack_f2(1.0f, fmaf(P, carry, L));

        float s = carry;
        sq_s[0*128 + ch] = s;  s = fmaf(E0.x, s, E0.y);
        sq_s[1*128 + ch] = s;  s = fmaf(E1.x, s, E1.y);
        sq_s[2*128 + ch] = s;  s = fmaf(E2.x, s, E2.y);
        sq_s[3*128 + ch] = s;
    }
    __syncthreads();

    // ---- phase B: replay sub-chunks with entry state, STG direct (512 tasks) ----
    {
        const int ch = tid & 127;
        const int qb = (tid >> 7) * 2;
        float* og = out + ((size_t)(b*T_ + t0)) * W_ + h * 128 + ch;
        #pragma unroll
        for (int e = 0; e < 2; ++e) {
            const int q = qb + e;
            float hh = sq_s[q*128 + ch];
            #pragma unroll
            for (int t = 0; t < SS; ++t) {
                float2 v = anx[(q*SS + t)*AXS + ch];
                hh = fmaf(v.x, hh, v.y);
                og[(size_t)(q*SS + t) * W_] = hh;
            }
        }
    }
}

// ---------------- launch ----------------
extern "C" void kernel_launch(void* const* d_in, const int* in_sizes, int n_in,
                              void* d_out, int out_size)
{
    const float* x       = (const float*)d_in[0];
    const int*   segp    = (const int*)  d_in[1];
    const float* a_param = (const float*)d_in[2];
    const float* w_in    = (const float*)d_in[3];
    const float* b_in    = (const float*)d_in[4];
    const float* w_a     = (const float*)d_in[5];
    const float* b_a     = (const float*)d_in[6];
    float* out = (float*)d_out;

    // 33792 + 66560 + 1024 + 512 + 4096 + 2048 + 256 = 108288
    const int smem_bytes = 64*XS*4 + 64*AXS*8 + 256*4 + 128*4 + NS*128*8 + NS*128*4 + 64*4;
    cudaFuncSetAttribute(fused_kernel,
                         cudaFuncAttributeMaxDynamicSharedMemorySize, smem_bytes);

    prep_kernel<<<128, 256>>>(w_in, w_a);
    fused_kernel<<<dim3(NCH, H_, B_), 256, smem_bytes>>>(x, segp, a_param,
                                                         b_in, b_a, out);
}

// round 17
// speedup vs baseline: 1.4169x; 1.0164x over previous
#include <cuda_runtime.h>
#include <cstdint>

// Problem constants
#define B_  4
#define T_  4096
#define W_  1024
#define H_  8

// Fused tiling: block = (chunk of 64 timesteps) x (1 head = 128 ch x 2 gates)
#define CL  64
#define NCH (T_/CL)        // 64 chunks
#define XS  132            // x_s row stride (floats): A-frag bank 4*lr+lc, conflict-free
#define AXS 132            // anx row stride (float2): epi STS.64 bank 8*lr+2*lcq, conflict-free
#define SS  16             // sub-chunk length
#define NS  (CL/SS)        // 4 sub-chunks

typedef unsigned long long ull;

// Device scratch (no allocations allowed)
// g_wp4[(((h*16+ks)*4+nq)*4+np)*32 + lane]: per (ks,nq,np) one warp LDG.128 = 512 contiguous B
__device__ float4 g_wp4[(size_t)H_*16*4*4*32];    // 1 MB
__device__ ull    g_loc[(size_t)B_*H_*NCH*128];   // per-chunk local (P,L)
__device__ ull    g_inc[(size_t)B_*H_*NCH*128];   // per-chunk inclusive (1, h_incl)

// ---------------- helpers ----------------
__device__ __forceinline__ uint32_t f2tf32(float f) {
    uint32_t r; asm("cvt.rna.tf32.f32 %0, %1;" : "=r"(r) : "f"(f)); return r;
}
__device__ __forceinline__ void mma_tf32(float4 &d, const uint32_t a[4],
                                         uint32_t b0, uint32_t b1) {
    asm("mma.sync.aligned.m16n8k8.row.col.f32.tf32.tf32.f32 "
        "{%0,%1,%2,%3}, {%4,%5,%6,%7}, {%8,%9}, {%0,%1,%2,%3};"
        : "+f"(d.x), "+f"(d.y), "+f"(d.z), "+f"(d.w)
        : "r"(a[0]), "r"(a[1]), "r"(a[2]), "r"(a[3]), "r"(b0), "r"(b1));
}
__device__ __forceinline__ float fast_tanh(float x) {
    float r; asm("tanh.approx.f32 %0, %1;" : "=f"(r) : "f"(x)); return r;
}
__device__ __forceinline__ float fast_sigmoid(float x) {
    return fmaf(fast_tanh(0.5f * x), 0.5f, 0.5f);
}
__device__ __forceinline__ float fast_sqrt(float x) {
    float r; asm("sqrt.approx.f32 %0, %1;" : "=f"(r) : "f"(x)); return r;
}
__device__ __forceinline__ ull pack_f2(float a, float b) {
    ull r;
    asm("mov.b64 %0, {%1, %2};" : "=l"(r) : "r"(__float_as_uint(a)), "r"(__float_as_uint(b)));
    return r;
}
__device__ __forceinline__ float lo_f(ull v) { return __uint_as_float((unsigned)(v & 0xffffffffull)); }
__device__ __forceinline__ float hi_f(ull v) { return __uint_as_float((unsigned)(v >> 32)); }

// ---------------- K0: pack weight table (coalesced float4) + init sentinels ----------------
__global__ __launch_bounds__(256)
void prep_kernel(const float* __restrict__ w_in, const float* __restrict__ w_a)
{
    const int gid = blockIdx.x * 256 + threadIdx.x;    // grid 128 -> 32768 threads
    #pragma unroll
    for (int e = 0; e < 2; ++e) {
        int idx = e * 32768 + gid;                     // < 65536 float4 slots
        int lane = idx & 31;
        int np   = (idx >> 5) & 3;
        int nq   = (idx >> 7) & 3;
        int ks   = (idx >> 9) & 15;
        int h    = idx >> 13;
        int lr  = lane >> 2, lcq = lane & 3;
        int k0  = ks * 8;
        float4 o;
        #pragma unroll
        for (int half = 0; half < 2; ++half) {
            int n  = nq*64 + np*16 + lr + half*8;
            int ch = n >> 1;
            const float* src = (n & 1) ? w_a : w_in;
            float v0 = src[h*16384 + (k0 + lcq)*128 + ch];
            float v1 = src[h*16384 + (k0 + lcq + 4)*128 + ch];
            if (half == 0) { o.x = __uint_as_float(f2tf32(v0)); o.y = __uint_as_float(f2tf32(v1)); }
            else           { o.z = __uint_as_float(f2tf32(v0)); o.w = __uint_as_float(f2tf32(v1)); }
        }
        g_wp4[idx] = o;
    }
    const ull sent = pack_f2(-1.0f, 0.0f);
    #pragma unroll
    for (int e = 0; e < 8; ++e) {
        int idx = e * 32768 + gid;                     // 262144 slots each
        g_loc[idx] = sent;
        g_inc[idx] = sent;
    }
}

// ---------------- K1: fused gates GEMM + scan (two-flag decoupled lookback) ----------------
// Grid (NCH, H, B), chunk index fastest -> lookback predecessors have lower bid.
__global__ __launch_bounds__(256, 2)
void fused_kernel(const float* __restrict__ x, const int* __restrict__ segp,
                  const float* __restrict__ a_param,
                  const float* __restrict__ b_in, const float* __restrict__ b_a,
                  float* __restrict__ out)
{
    extern __shared__ float smem[];
    float*  x_s    = smem;                        // [64][XS] tf32 bits   33792 B
    float2* anx    = (float2*)(smem + 64*XS);     // [64][AXS] (a,nx)     67584 B
    float*  bias_s = (float*)(anx + 64*AXS);      // [256]
    float*  c_s    = bias_s + 256;                // [128]
    float2* Eq_s   = (float2*)(c_s + 128);        // [NS][128] sub-chunk summaries
    float*  sq_s   = (float*)(Eq_s + NS*128);     // [NS][128] sub-chunk entry states
    int*    seg_s  = (int*)(sq_s + NS*128);       // [64]

    const int tid = threadIdx.x;
    const int c = blockIdx.x, h = blockIdx.y, b = blockIdx.z;
    const int t0 = c * CL;
    const int bh = b * H_ + h;

    // ---- stage: x chunk (tf32), seg, bias, decay consts ----
    {
        const float* xg = x + ((size_t)(b*T_ + t0)) * W_ + h * 128;
        #pragma unroll
        for (int i = tid; i < 64*32; i += 256) {
            int m = i >> 5, q = i & 31;
            float4 v = *(const float4*)(xg + (size_t)m * W_ + q*4);
            float4 o;
            o.x = __uint_as_float(f2tf32(v.x));
            o.y = __uint_as_float(f2tf32(v.y));
            o.z = __uint_as_float(f2tf32(v.z));
            o.w = __uint_as_float(f2tf32(v.w));
            *(float4*)(x_s + m*XS + q*4) = o;
        }
        if (tid < 64)  seg_s[tid] = segp[b*T_ + t0 + tid];
        if (tid < 256) bias_s[tid] = (tid & 1) ? b_a[h*128 + (tid>>1)]
                                               : b_in[h*128 + (tid>>1)];
        if (tid < 128) c_s[tid] = -8.0f * log1pf(__expf(a_param[h*128 + tid]));
    }
    __syncthreads();

    // ---- MMA: z[64 t][256 n] = x[64][128] * w[128][256] ----
    const int warp = tid >> 5, lane = tid & 31;
    const int wm = (warp >> 2) * 32;
    const int nq = warp & 3;                   // n quadrant
    const int lr = lane >> 2, lcq = lane & 3;

    float4 acc[2][8];
    #pragma unroll
    for (int mf = 0; mf < 2; ++mf)
        #pragma unroll
        for (int nf = 0; nf < 8; ++nf)
            acc[mf][nf] = make_float4(0.f, 0.f, 0.f, 0.f);

    // coalesced weight pointer: + ks*512 + np*32 per step
    const float4* wbase = g_wp4 + ((size_t)h*256 + nq*4)*32 + lane;
    #pragma unroll
    for (int ks = 0; ks < 16; ++ks) {
        const int k0 = ks * 8;
        uint32_t a[2][4];
        #pragma unroll
        for (int mf = 0; mf < 2; ++mf) {
            const float* xr = x_s + (wm + mf*16 + lr)*XS + k0 + lcq;
            a[mf][0] = __float_as_uint(xr[0]);
            a[mf][1] = __float_as_uint(xr[8*XS]);
            a[mf][2] = __float_as_uint(xr[4]);
            a[mf][3] = __float_as_uint(xr[8*XS + 4]);
        }
        const float4* wk = wbase + ks*512;
        #pragma unroll
        for (int np = 0; np < 4; ++np) {
            float4 bv = __ldg(wk + np*32);
            uint32_t b0 = __float_as_uint(bv.x), b1 = __float_as_uint(bv.y);
            uint32_t b2 = __float_as_uint(bv.z), b3 = __float_as_uint(bv.w);
            mma_tf32(acc[0][2*np],   a[0], b0, b1);
            mma_tf32(acc[1][2*np],   a[1], b0, b1);
            mma_tf32(acc[0][2*np+1], a[0], b2, b3);
            mma_tf32(acc[1][2*np+1], a[1], b2, b3);
        }
    }

    // ---- epilogue: gates -> (a, normed_x) into smem (conflict-free STS.64) ----
    #pragma unroll
    for (int mf = 0; mf < 2; ++mf) {
        #pragma unroll
        for (int nf = 0; nf < 8; ++nf) {
            const int ch = nq*32 + nf*4 + lcq;
            const float bx = bias_s[2*ch];
            const float ba = bias_s[2*ch + 1];
            const float cc = c_s[ch];
            #pragma unroll
            for (int half = 0; half < 2; ++half) {
                const int r = wm + mf*16 + lr + half*8;
                const float zx = (half ? acc[mf][nf].z : acc[mf][nf].x) + bx;
                const float za = (half ? acc[mf][nf].w : acc[mf][nf].y) + ba;
                const float gx = fast_sigmoid(zx);
                const float ga = fast_sigmoid(za);
                const float la = cc * ga;
                const float av = __expf(la);
                const float mult = fast_sqrt(fmaxf(1.0f - av*av, 0.0f));
                const float xv = x_s[r*XS + ch];
                const float nx = xv * gx * mult;
                const float ao = (seg_s[r] == 0) ? 0.0f : av;
                anx[r*AXS + ch] = make_float2(ao, nx);
            }
        }
    }
    __syncthreads();

    // ---- phase A: sub-chunk summaries, one (ch-pair, q) task per thread,
    //      (a,nx) cached in registers for the replay ----
    const int chp = tid & 63;          // channel pair index
    const int qq  = tid >> 6;          // sub-chunk 0..3
    const int ch0 = chp * 2;
    float4 v[SS];                      // 64 regs: (a0,nx0,a1,nx1) per t
    {
        float P0 = 1.0f, L0 = 0.0f, P1 = 1.0f, L1 = 0.0f;
        #pragma unroll
        for (int t = 0; t < SS; ++t) {
            v[t] = *(const float4*)(&anx[(qq*SS + t)*AXS + ch0]);
            L0 = fmaf(v[t].x, L0, v[t].y);  P0 *= v[t].x;
            L1 = fmaf(v[t].z, L1, v[t].w);  P1 *= v[t].z;
        }
        Eq_s[qq*128 + ch0]     = make_float2(P0, L0);
        Eq_s[qq*128 + ch0 + 1] = make_float2(P1, L1);
    }
    __syncthreads();

    // ---- combine, publish, lookback, sub-chunk entry states (128 threads) ----
    if (tid < 128) {
        const int ch = tid;
        float2 E0 = Eq_s[0*128 + ch], E1 = Eq_s[1*128 + ch];
        float2 E2 = Eq_s[2*128 + ch], E3 = Eq_s[3*128 + ch];
        float P = E0.x, L = E0.y;
        L = fmaf(E1.x, L, E1.y); P *= E1.x;
        L = fmaf(E2.x, L, E2.y); P *= E2.x;
        L = fmaf(E3.x, L, E3.y); P *= E3.x;

        const size_t slot = ((size_t)bh * NCH + c) * 128 + ch;
        *(volatile ull*)&g_loc[slot] = pack_f2(P, L);   // publish local ASAP

        float carry = 0.0f;
        if (c > 0) {
            float Aacc = 1.0f, Hacc = 0.0f;
            int k = c - 1;
            const ull* incp = g_inc + (size_t)bh * NCH * 128 + ch;
            const ull* locp = g_loc + (size_t)bh * NCH * 128 + ch;
            while (true) {
                ull vv = *(volatile const ull*)(incp + (size_t)k * 128);
                if (lo_f(vv) >= 0.0f) { carry = fmaf(Aacc, hi_f(vv), Hacc); break; }
                ull w = *(volatile const ull*)(locp + (size_t)k * 128);
                float Pk = lo_f(w);
                if (Pk >= 0.0f) {
                    Hacc = fmaf(Aacc, hi_f(w), Hacc);
                    Aacc *= Pk;
                    if (--k < 0) { carry = Hacc; break; }
                }
            }
        }
        *(volatile ull*)&g_inc[slot] = pack_f2(1.0f, fmaf(P, carry, L));

        float s = carry;
        sq_s[0*128 + ch] = s;  s = fmaf(E0.x, s, E0.y);
        sq_s[1*128 + ch] = s;  s = fmaf(E1.x, s, E1.y);
        sq_s[2*128 + ch] = s;  s = fmaf(E2.x, s, E2.y);
        sq_s[3*128 + ch] = s;
    }
    __syncthreads();

    // ---- phase B: replay from registers, STG.64 coalesced ----
    {
        float h0 = sq_s[qq*128 + ch0];
        float h1 = sq_s[qq*128 + ch0 + 1];
        float* og = out + ((size_t)(b*T_ + t0 + qq*SS)) * W_ + h * 128 + ch0;
        #pragma unroll
        for (int t = 0; t < SS; ++t) {
            h0 = fmaf(v[t].x, h0, v[t].y);
            h1 = fmaf(v[t].z, h1, v[t].w);
            *(float2*)(og + (size_t)t * W_) = make_float2(h0, h1);
        }
    }
}

// ---------------- launch ----------------
extern "C" void kernel_launch(void* const* d_in, const int* in_sizes, int n_in,
                              void* d_out, int out_size)
{
    const float* x       = (const float*)d_in[0];
    const int*   segp    = (const int*)  d_in[1];
    const float* a_param = (const float*)d_in[2];
    const float* w_in    = (const float*)d_in[3];
    const float* b_in    = (const float*)d_in[4];
    const float* w_a     = (const float*)d_in[5];
    const float* b_a     = (const float*)d_in[6];
    float* out = (float*)d_out;

    // 33792 + 67584 + 1024 + 512 + 4096 + 2048 + 256 = 109312
    const int smem_bytes = 64*XS*4 + 64*AXS*8 + 256*4 + 128*4 + NS*128*8 + NS*128*4 + 64*4;
    cudaFuncSetAttribute(fused_kernel,
                         cudaFuncAttributeMaxDynamicSharedMemorySize, smem_bytes);

    prep_kernel<<<128, 256>>>(w_in, w_a);
    fused_kernel<<<dim3(NCH, H_, B_), 256, smem_bytes>>>(x, segp, a_param,
                                                         b_in, b_a, out);
}